// round 17
// baseline (speedup 1.0000x reference)
#include <cuda_runtime.h>
#include <cuda_fp16.h>
#include <math.h>
#include <cstdint>

#define Bn 4
#define CI 128
#define CO 128
#define Hn 128
#define Wn 128
#define HW (Hn*Wn)
#define KK 9
#define CIPH 144         // fp16 per pixel row (128 + 16 pad) = 288B = 72 words (≡8 mod 32)
#define BUFH (130*CIPH)  // single buffer, halfs (130 rows: Phase A halo)

// warp-level tensor core MMA: D(16x8,f32) += A(16x16,f16) * B(16x8,f16)
__device__ __forceinline__ void mma_f16(float* c, const uint4& a, uint32_t b0, uint32_t b1) {
    asm volatile("mma.sync.aligned.m16n8k16.row.col.f32.f16.f16.f32 "
        "{%0,%1,%2,%3}, {%4,%5,%6,%7}, {%8,%9}, {%0,%1,%2,%3};"
        : "+f"(c[0]), "+f"(c[1]), "+f"(c[2]), "+f"(c[3])
        : "r"(a.x), "r"(a.y), "r"(a.z), "r"(a.w), "r"(b0), "r"(b1));
}

// channel c -> storage slot: within each 16-group, slots hold channels
// (0,1),(8,9),(2,3),(10,11),(4,5),(12,13),(6,7),(14,15) so each lane's
// B fragment (k=2j,2j+1,2j+8,2j+9) is one contiguous 8-byte LDS.64.
__device__ __forceinline__ int slot16(int c) {
    return (c & ~15) | (((c >> 1) & 3) << 2) | (((c >> 3) & 1) << 1) | (c & 1);
}

// ---------------- scratch ----------------
__device__ __align__(16) __half g_xTh[Bn*HW*CI];     // x NHWC, fp16, slot-permuted
__device__ uint4 g_wFh[KK*8*8*32];                   // w_dcn A-frags (fp16, k16)
__device__ uint4 g_wOffFh[KK*8*2*32];                // w_off A-frags (fp16, M=32 pad)
__device__ __align__(16) __half g_convh[Bn*CO*HW];   // pre-BN output (fp16)
__device__ float g_stat[2*CO];
__device__ float g_scale[CO];   // unused (kept for ABI stability)
__device__ float g_shift[CO];

// ---------------- K1: NCHW fp32 -> NHWC fp16 slot-permuted ----------------
__global__ void k_transpose_x(const float* __restrict__ in) {
    __shared__ float t[32][33];
    int wb = blockIdx.x * 32, cb = blockIdx.y * 32;
    int by = blockIdx.z;
    int b = by >> 7, y = by & 127;
    t[threadIdx.y][threadIdx.x] =
        in[((b*CI + cb + threadIdx.y)*Hn + y)*Wn + wb + threadIdx.x];
    __syncthreads();
    int c = cb + threadIdx.x;
    g_xTh[(size_t)(by*Wn + wb + threadIdx.y)*CI + slot16(c)] =
        __float2half(t[threadIdx.x][threadIdx.y]);
}

// ---------------- K2a: w_dcn -> fp16 A-fragment prepack; zero g_stat ----------------
__global__ void k_prep_w(const float* __restrict__ w) {
    if (blockIdx.x == 0 && threadIdx.x < 2*CO) g_stat[threadIdx.x] = 0.f;
    int i = blockIdx.x * blockDim.x + threadIdx.x;
    if (i >= KK*8*8*32) return;
    int l = i & 31;
    int r = i >> 5;
    int ost = r & 7;  r >>= 3;
    int s = r & 7;
    int tap = r >> 3;
    int o = ost*16 + (l >> 2);
    int c0 = s*16 + (l & 3)*2;
    const float* w0 = w + ((size_t)o*CI)*9 + tap;
    const float* w1 = w + ((size_t)(o+8)*CI)*9 + tap;
    __half2 a0 = __floats2half2_rn(w0[c0*9],     w0[(c0+1)*9]);
    __half2 a1 = __floats2half2_rn(w1[c0*9],     w1[(c0+1)*9]);
    __half2 a2 = __floats2half2_rn(w0[(c0+8)*9], w0[(c0+9)*9]);
    __half2 a3 = __floats2half2_rn(w1[(c0+8)*9], w1[(c0+9)*9]);
    uint4 u;
    u.x = *(uint32_t*)&a0; u.y = *(uint32_t*)&a1;
    u.z = *(uint32_t*)&a2; u.w = *(uint32_t*)&a3;
    g_wFh[i] = u;
}

// ---------------- K2b: w_off -> fp16 A-fragment prepack (18 rows padded to 32) ----------------
__global__ void k_prep_woff(const float* __restrict__ w) {
    int i = blockIdx.x * blockDim.x + threadIdx.x;
    if (i >= KK*8*2*32) return;
    int l   = i & 31;
    int ost = (i >> 5) & 1;
    int s   = (i >> 6) & 7;
    int tap = i >> 9;
    int o = ost*16 + (l >> 2);
    int c0 = s*16 + (l & 3)*2;
    float v00 = 0.f, v01 = 0.f, v08 = 0.f, v09 = 0.f;
    float v10 = 0.f, v11 = 0.f, v18 = 0.f, v19 = 0.f;
    if (o < 18) {
        const float* w0 = w + ((size_t)o*CI)*9 + tap;
        v00 = w0[c0*9]; v01 = w0[(c0+1)*9]; v08 = w0[(c0+8)*9]; v09 = w0[(c0+9)*9];
    }
    if (o + 8 < 18) {
        const float* w1 = w + ((size_t)(o+8)*CI)*9 + tap;
        v10 = w1[c0*9]; v11 = w1[(c0+1)*9]; v18 = w1[(c0+8)*9]; v19 = w1[(c0+9)*9];
    }
    __half2 a0 = __floats2half2_rn(v00, v01);
    __half2 a1 = __floats2half2_rn(v10, v11);
    __half2 a2 = __floats2half2_rn(v08, v09);
    __half2 a3 = __floats2half2_rn(v18, v19);
    uint4 u;
    u.x = *(uint32_t*)&a0; u.y = *(uint32_t*)&a1;
    u.z = *(uint32_t*)&a2; u.w = *(uint32_t*)&a3;
    g_wOffFh[i] = u;
}

// ---------------- K4: fused offset-conv + deformable sampling + f16 MMA + BN stats ----------------
// block = (h, b): 128 pixels x 128 out channels. 256 threads = 8 warps.
// Single buffer + 3 resident blocks (forced 85 regs via launch_bounds).
#define OFF_OFF  (BUFH*2)                // byte offset 37440
#define SMEM_K4  (OFF_OFF + 9216)        // + float[18][128] offsets = 46656 B

__global__ __launch_bounds__(256, 3) void k_main(const float* __restrict__ b_off) {
    extern __shared__ __align__(16) char smem[];
    __half* sB   = (__half*)smem;         // [130][CIPH]
    float*  sOff = (float*)(smem + OFF_OFF);

    const int h   = blockIdx.x;
    const int b   = blockIdx.y;
    const int tid = threadIdx.x;
    const int wid = tid >> 5;
    const int l   = tid & 31;

    // ================= Phase A: offset conv (18 x 128) via m16n8k16 =================
    {
        const int wo = wid >> 2;          // 0..1 (o-stripe of 16)
        const int wp = wid & 3;           // 0..3 (32-px group)
        float accO[4][4];
#pragma unroll
        for (int t = 0; t < 4; t++)
#pragma unroll
            for (int j = 0; j < 4; j++) accO[t][j] = 0.f;

        for (int r = 0; r < 3; r++) {
            if (r) __syncthreads();       // protect sB from previous row's readers
            const int yy = h - 1 + r;
            const bool yok = (yy >= 0 && yy < Hn);
            for (int i = tid; i < 130*16; i += 256) {
                int p = i >> 4, q = i & 15;
                int sx = p - 1;
                uint4 u = make_uint4(0u, 0u, 0u, 0u);
                if (yok && sx >= 0 && sx < Wn)
                    u = *(const uint4*)(g_xTh + (size_t)(b*HW + yy*Wn + sx)*CI + q*8);
                *(uint4*)(sB + p*CIPH + q*8) = u;
            }
            __syncthreads();
            const __half* bBaseO = sB + (wp*32 + (l >> 2))*CIPH + (l & 3)*4;
#pragma unroll
            for (int kx = 0; kx < 3; kx++) {
                int k = 3*r + kx;
                const uint4* aBase = g_wOffFh + ((k*8)*2 + wo)*32 + l;
                const __half* bShift = bBaseO + kx*CIPH;
#pragma unroll
                for (int s = 0; s < 8; s++) {
                    uint4 aF = aBase[s*64];
                    const __half* bp = bShift + s*16;
#pragma unroll
                    for (int t = 0; t < 4; t++) {
                        uint2 bv = *(const uint2*)(bp + t*8*CIPH);
                        mma_f16(accO[t], aF, bv.x, bv.y);
                    }
                }
            }
        }

        int o0  = wo*16 + (l >> 2);
        int px0 = wp*32 + 2*(l & 3);
        float bo0 = (o0     < 18) ? b_off[o0]     : 0.f;
        float bo1 = (o0 + 8 < 18) ? b_off[o0 + 8] : 0.f;
#pragma unroll
        for (int t = 0; t < 4; t++) {
            int px = px0 + t*8;
            if (o0 < 18) {
                sOff[o0*128 + px]     = accO[t][0] + bo0;
                sOff[o0*128 + px + 1] = accO[t][1] + bo0;
            }
            if (o0 + 8 < 18) {
                sOff[(o0 + 8)*128 + px]     = accO[t][2] + bo1;
                sOff[(o0 + 8)*128 + px + 1] = accO[t][3] + bo1;
            }
        }
    }
    __syncthreads();   // sOff ready; Phase-A buffer reads complete

    // ================= Phase B: deformable sampling + main GEMM =================
    const int wm  = wid >> 1;
    const int wc  = wid & 1;

    float acc[2][8][4];
#pragma unroll
    for (int st = 0; st < 2; st++)
#pragma unroll
        for (int t = 0; t < 8; t++)
#pragma unroll
            for (int j = 0; j < 4; j++) acc[st][t][j] = 0.f;

    const int spix  = tid >> 3;           // sampler: pixel 0..31 (per pass)
    const int lane8 = tid & 7;

    for (int k = 0; k < KK; k++) {
        if (k) __syncthreads();           // protect sB from previous tap's readers
        const int ky = k / 3, kx = k % 3;
        const float* dyp = sOff + (2*k)*128;
        const float* dxp = sOff + (2*k + 1)*128;
#pragma unroll
        for (int pass = 0; pass < 4; pass++) {
            int px = pass*32 + spix;
            float dy = dyp[px];
            float dx = dxp[px];
            float ys = (float)(h - 1 + ky) + dy;
            float xs = (float)(px - 1 + kx) + dx;
            float y0f = floorf(ys), x0f = floorf(xs);
            float wy = ys - y0f, wx = xs - x0f;
            int y0 = (int)y0f, x0 = (int)x0f;
            int y1 = y0 + 1, x1 = x0 + 1;
            float vy0 = (y0 >= 0 && y0 < Hn) ? 1.f : 0.f;
            float vy1 = (y1 >= 0 && y1 < Hn) ? 1.f : 0.f;
            float vx0 = (x0 >= 0 && x0 < Wn) ? 1.f : 0.f;
            float vx1 = (x1 >= 0 && x1 < Wn) ? 1.f : 0.f;
            int y0c = min(max(y0, 0), Hn-1), y1c = min(max(y1, 0), Hn-1);
            int x0c = min(max(x0, 0), Wn-1), x1c = min(max(x1, 0), Wn-1);
            int base = b * HW;
            int i0 = (base + y0c*Wn + x0c)*CI;
            int i1 = (base + y0c*Wn + x1c)*CI;
            int i2 = (base + y1c*Wn + x0c)*CI;
            int i3 = (base + y1c*Wn + x1c)*CI;
            __half2 W00 = __float2half2_rn((1.f - wy)*(1.f - wx)*vy0*vx0);
            __half2 W01 = __float2half2_rn((1.f - wy)*wx       *vy0*vx1);
            __half2 W10 = __float2half2_rn(wy       *(1.f - wx)*vy1*vx0);
            __half2 W11 = __float2half2_rn(wy       *wx        *vy1*vx1);
#pragma unroll
            for (int cc = 0; cc < CI; cc += 64) {
                int c = cc + lane8*8;     // 8 slots per lane
                // pairwise corner processing: lower peak register pressure
                uint4 u0 = *(const uint4*)(g_xTh + i0 + c);
                uint4 u1 = *(const uint4*)(g_xTh + i1 + c);
                __half2 r0 = __hfma2(W01, ((const __half2*)&u1)[0], __hmul2(W00, ((const __half2*)&u0)[0]));
                __half2 r1 = __hfma2(W01, ((const __half2*)&u1)[1], __hmul2(W00, ((const __half2*)&u0)[1]));
                __half2 r2 = __hfma2(W01, ((const __half2*)&u1)[2], __hmul2(W00, ((const __half2*)&u0)[2]));
                __half2 r3 = __hfma2(W01, ((const __half2*)&u1)[3], __hmul2(W00, ((const __half2*)&u0)[3]));
                uint4 u2 = *(const uint4*)(g_xTh + i2 + c);
                uint4 u3 = *(const uint4*)(g_xTh + i3 + c);
                r0 = __hfma2(W11, ((const __half2*)&u3)[0], __hfma2(W10, ((const __half2*)&u2)[0], r0));
                r1 = __hfma2(W11, ((const __half2*)&u3)[1], __hfma2(W10, ((const __half2*)&u2)[1], r1));
                r2 = __hfma2(W11, ((const __half2*)&u3)[2], __hfma2(W10, ((const __half2*)&u2)[2], r2));
                r3 = __hfma2(W11, ((const __half2*)&u3)[3], __hfma2(W10, ((const __half2*)&u2)[3], r3));
                uint4 outv;
                ((__half2*)&outv)[0] = r0;
                ((__half2*)&outv)[1] = r1;
                ((__half2*)&outv)[2] = r2;
                ((__half2*)&outv)[3] = r3;
                *(uint4*)(sB + px*CIPH + c) = outv;
            }
        }
        __syncthreads();

        // --- GEMM: 8 K=16 steps; per step 2 A-frag LDG.128 + 8 B LDS.64 ---
        const __half* bBase = sB + (wc*64 + (l >> 2))*CIPH + (l & 3)*4;
        const uint4* aBase = g_wFh + ((k*8)*8 + 2*wm)*32 + l;
#pragma unroll
        for (int s = 0; s < 8; s++) {
            uint4 aF0 = aBase[s*256];          // ostripe 2*wm
            uint4 aF1 = aBase[s*256 + 32];     // ostripe 2*wm + 1
            const __half* bp = bBase + s*16;
#pragma unroll
            for (int t = 0; t < 8; t++) {
                uint2 bv = *(const uint2*)(bp + t*8*CIPH);
                mma_f16(acc[0][t], aF0, bv.x, bv.y);
                mma_f16(acc[1][t], aF1, bv.x, bv.y);
            }
        }
    }

    // --- epilogue: D[o][pix] fragments -> g_convh (NCHW, fp16) ---
#pragma unroll
    for (int st = 0; st < 2; st++) {
        int o = 32*wm + st*16 + (l >> 2);
#pragma unroll
        for (int t = 0; t < 8; t++) {
            int px = wc*64 + t*8 + 2*(l & 3);
            __half* d = g_convh + ((size_t)(b*CO + o)*Hn + h)*Wn + px;
            *(__half2*)d          = __floats2half2_rn(acc[st][t][0], acc[st][t][1]);
            *(__half2*)(d + 8*HW) = __floats2half2_rn(acc[st][t][2], acc[st][t][3]);
        }
    }

    // --- fused BN stats: quad-reduce, atomic (from fp32 registers) ---
    {
        float s[4] = {0.f, 0.f, 0.f, 0.f};
        float q[4] = {0.f, 0.f, 0.f, 0.f};
#pragma unroll
        for (int st = 0; st < 2; st++)
#pragma unroll
            for (int t = 0; t < 8; t++) {
                float a0 = acc[st][t][0], a1 = acc[st][t][1];
                float a2 = acc[st][t][2], a3 = acc[st][t][3];
                s[2*st]   += a0 + a1;  q[2*st]   += a0*a0 + a1*a1;
                s[2*st+1] += a2 + a3;  q[2*st+1] += a2*a2 + a3*a3;
            }
#pragma unroll
        for (int d = 1; d < 4; d <<= 1)
#pragma unroll
            for (int j = 0; j < 4; j++) {
                s[j] += __shfl_xor_sync(0xffffffffu, s[j], d);
                q[j] += __shfl_xor_sync(0xffffffffu, q[j], d);
            }
        if ((l & 3) == 0) {
            int o0 = 32*wm + (l >> 2);
#pragma unroll
            for (int j = 0; j < 4; j++) {
                int o = o0 + 8*j;
                atomicAdd(&g_stat[o], s[j]);
                atomicAdd(&g_stat[CO + o], q[j]);
            }
        }
    }
}

// ---------------- K6: apply BN + ReLU (fp16 in, fp32 out; finalize inlined) ----------------
__global__ void k_bn_apply(float* __restrict__ out,
                           const float* __restrict__ gamma,
                           const float* __restrict__ beta) {
    int i = blockIdx.x * blockDim.x + threadIdx.x;   // 8-half chunk index
    int ch = (i >> 11) & 127;                        // plane = 16384 halfs = 2048 chunks
    float inv_n = 1.f / (float)(Bn*HW);
    float mean = g_stat[ch] * inv_n;
    float var  = g_stat[CO + ch] * inv_n - mean*mean;
    float r = rsqrtf(var + 0.001f);
    float sc = gamma[ch] * r;
    float sh = beta[ch] - mean*sc;
    uint4 u = ((const uint4*)g_convh)[i];
    float4 o0, o1;
    float2 f;
    f = __half22float2(((const __half2*)&u)[0]);
    o0.x = fmaxf(fmaf(f.x, sc, sh), 0.f); o0.y = fmaxf(fmaf(f.y, sc, sh), 0.f);
    f = __half22float2(((const __half2*)&u)[1]);
    o0.z = fmaxf(fmaf(f.x, sc, sh), 0.f); o0.w = fmaxf(fmaf(f.y, sc, sh), 0.f);
    f = __half22float2(((const __half2*)&u)[2]);
    o1.x = fmaxf(fmaf(f.x, sc, sh), 0.f); o1.y = fmaxf(fmaf(f.y, sc, sh), 0.f);
    f = __half22float2(((const __half2*)&u)[3]);
    o1.z = fmaxf(fmaf(f.x, sc, sh), 0.f); o1.w = fmaxf(fmaf(f.y, sc, sh), 0.f);
    ((float4*)out)[2*i]     = o0;
    ((float4*)out)[2*i + 1] = o1;
}

// ---------------- launch ----------------
extern "C" void kernel_launch(void* const* d_in, const int* in_sizes, int n_in,
                              void* d_out, int out_size) {
    const float* x     = (const float*)d_in[0];
    const float* w_off = (const float*)d_in[1];
    const float* b_off = (const float*)d_in[2];
    const float* w_dcn = (const float*)d_in[3];
    const float* gamma = (const float*)d_in[4];
    const float* beta  = (const float*)d_in[5];
    float* out = (float*)d_out;

    cudaFuncSetAttribute(k_main, cudaFuncAttributeMaxDynamicSharedMemorySize, SMEM_K4);

    k_transpose_x<<<dim3(Wn/32, CI/32, Bn*Hn), dim3(32, 32)>>>(x);
    k_prep_w<<<(KK*8*8*32 + 255)/256, 256>>>(w_dcn);
    k_prep_woff<<<(KK*8*2*32 + 255)/256, 256>>>(w_off);
    k_main<<<dim3(Hn, Bn), 256, SMEM_K4>>>(b_off);
    k_bn_apply<<<(Bn*CO*HW/8)/256, 256>>>(out, gamma, beta);
}